// round 16
// baseline (speedup 1.0000x reference)
#include <cuda_runtime.h>

#define SS   224
#define PP   30
#define CROPV 164
#define BB   16
#define TT   16
#define TG   4                             // frames per thread
#define NTG  (TT / TG)                     // 4 t-groups
#define J8   (SS / 8)                      // 28 float8 groups per row
#define TOTAL_THREADS (BB * 3 * SS * J8 * NTG)   // 1204224 = 4704 * 256

// 256-bit global load (sm_100+): 8 consecutive floats, non-coherent path
__device__ __forceinline__ void ldg256(const float* p, float4& a, float4& b) {
    asm volatile("ld.global.nc.v8.f32 {%0,%1,%2,%3,%4,%5,%6,%7}, [%8];"
        : "=f"(a.x), "=f"(a.y), "=f"(a.z), "=f"(a.w),
          "=f"(b.x), "=f"(b.y), "=f"(b.z), "=f"(b.w)
        : "l"(p));
}

// 256-bit global store (sm_100+)
__device__ __forceinline__ void stg256(float* p, float4 a, float4 b) {
    asm volatile("st.global.v8.f32 [%0], {%1,%2,%3,%4,%5,%6,%7,%8};"
        :: "l"(p),
           "f"(a.x), "f"(a.y), "f"(a.z), "f"(a.w),
           "f"(b.x), "f"(b.y), "f"(b.z), "f"(b.w)
        : "memory");
}

__global__ __launch_bounds__(256) void prompter_add_kernel(
    const float* __restrict__ x,        // [B,3,T,S,S]
    const float* __restrict__ pu,       // [3,3,2P,S]
    const float* __restrict__ pd,       // [3,3,P,S]
    const float* __restrict__ pl,       // [3,3,CROP,2P]
    const float* __restrict__ pr,       // [3,3,CROP,P]
    const int*   __restrict__ cams,     // [B]
    const int*   __restrict__ offs_r,   // [B]
    const int*   __restrict__ offs_d,   // [B]
    float* __restrict__ out)            // [B,3,T,S,S]
{
    int tid = blockIdx.x * blockDim.x + threadIdx.x;

    int j8 = tid % J8;
    int i  = (tid / J8) % SS;
    int c  = (tid / (J8 * SS)) % 3;
    int b  = (tid / (J8 * SS * 3)) % BB;
    int tg =  tid / (J8 * SS * 3 * BB);
    int j  = j8 * 8;

    int cam = cams[b];
    int orr = offs_r[b];
    int od  = offs_d[b];
    int off_l = 2 * PP - orr;   // [30,59]
    int off_u = 2 * PP - od;    // [30,59]

    float4 pv0, pv1;            // prompt for 8 columns

    if (i < off_u) {
        // top band: vertical interp between two rows of pad_up (in_size=60)
        float scale = 60.0f / (float)off_u;
        float f = fmaxf(((float)i + 0.5f) * scale - 0.5f, 0.0f);
        int   r0 = (int)floorf(f);
        float w  = f - (float)r0;
        int   r1 = min(r0 + 1, 59);
        const float* row0 = pu + ((size_t)(cam * 3 + c) * 60 + r0) * SS + j;
        const float* row1 = pu + ((size_t)(cam * 3 + c) * 60 + r1) * SS + j;
        float4 a0 = __ldg((const float4*)row0);
        float4 a1 = __ldg((const float4*)row0 + 1);
        float4 d0 = __ldg((const float4*)row1);
        float4 d1 = __ldg((const float4*)row1 + 1);
        float om = 1.0f - w;
        pv0.x = a0.x * om + d0.x * w; pv0.y = a0.y * om + d0.y * w;
        pv0.z = a0.z * om + d0.z * w; pv0.w = a0.w * om + d0.w * w;
        pv1.x = a1.x * om + d1.x * w; pv1.y = a1.y * om + d1.y * w;
        pv1.z = a1.z * om + d1.z * w; pv1.w = a1.w * om + d1.w * w;
    } else if (i >= SS - od) {
        // bottom band: vertical interp between two rows of pad_down (in_size=30)
        float scale = 30.0f / (float)od;
        float pos = (float)(i - (SS - od));
        float f = fmaxf((pos + 0.5f) * scale - 0.5f, 0.0f);
        int   r0 = (int)floorf(f);
        float w  = f - (float)r0;
        int   r1 = min(r0 + 1, 29);
        const float* row0 = pd + ((size_t)(cam * 3 + c) * 30 + r0) * SS + j;
        const float* row1 = pd + ((size_t)(cam * 3 + c) * 30 + r1) * SS + j;
        float4 a0 = __ldg((const float4*)row0);
        float4 a1 = __ldg((const float4*)row0 + 1);
        float4 d0 = __ldg((const float4*)row1);
        float4 d1 = __ldg((const float4*)row1 + 1);
        float om = 1.0f - w;
        pv0.x = a0.x * om + d0.x * w; pv0.y = a0.y * om + d0.y * w;
        pv0.z = a0.z * om + d0.z * w; pv0.w = a0.w * om + d0.w * w;
        pv1.x = a1.x * om + d1.x * w; pv1.y = a1.y * om + d1.y * w;
        pv1.z = a1.z * om + d1.z * w; pv1.w = a1.w * om + d1.w * w;
    } else {
        // middle band: horizontal interp (left pad / zero / right pad), row r
        int r = i - off_u;                 // [0, CROP)
        const float* lrow = pl + ((size_t)(cam * 3 + c) * CROPV + r) * (2 * PP);
        const float* rrow = pr + ((size_t)(cam * 3 + c) * CROPV + r) * PP;
        float vals[8];
        #pragma unroll
        for (int k = 0; k < 8; k++) {
            int jj = j + k;
            float v = 0.0f;
            if (jj < off_l) {
                float scale = 60.0f / (float)off_l;
                float f = fmaxf(((float)jj + 0.5f) * scale - 0.5f, 0.0f);
                int   c0 = (int)floorf(f);
                float w  = f - (float)c0;
                int   c1 = min(c0 + 1, 59);
                v = __ldg(lrow + c0) * (1.0f - w) + __ldg(lrow + c1) * w;
            } else if (jj >= SS - orr) {
                float scale = 30.0f / (float)orr;
                float pos = (float)(jj - (SS - orr));
                float f = fmaxf((pos + 0.5f) * scale - 0.5f, 0.0f);
                int   c0 = (int)floorf(f);
                float w  = f - (float)c0;
                int   c1 = min(c0 + 1, 29);
                v = __ldg(rrow + c0) * (1.0f - w) + __ldg(rrow + c1) * w;
            }
            vals[k] = v;
        }
        pv0.x = vals[0]; pv0.y = vals[1]; pv0.z = vals[2]; pv0.w = vals[3];
        pv1.x = vals[4]; pv1.y = vals[5]; pv1.z = vals[6]; pv1.w = vals[7];
    }

    // out[b,c,t,i,j..j+7] = x[...] + pv, for t in [tg*TG, tg*TG+TG)
    size_t base = ((((size_t)b * 3 + c) * TT) + (size_t)tg * TG) * (size_t)(SS * SS)
                + (size_t)i * SS + (size_t)j;
    const float* xin  = x + base;
    float*       oout = out + base;
    const int stride = SS * SS;            // float stride between frames

    #pragma unroll
    for (int t = 0; t < TG; t++) {
        float4 a, bb2;
        ldg256(xin + (size_t)t * stride, a, bb2);
        a.x  += pv0.x; a.y  += pv0.y; a.z  += pv0.z; a.w  += pv0.w;
        bb2.x += pv1.x; bb2.y += pv1.y; bb2.z += pv1.z; bb2.w += pv1.w;
        stg256(oout + (size_t)t * stride, a, bb2);
    }
}

extern "C" void kernel_launch(void* const* d_in, const int* in_sizes, int n_in,
                              void* d_out, int out_size) {
    const float* x   = (const float*)d_in[0];
    const float* pu  = (const float*)d_in[1];
    const float* pd  = (const float*)d_in[2];
    const float* pl  = (const float*)d_in[3];
    const float* pr  = (const float*)d_in[4];
    const int*   cam = (const int*)d_in[5];
    const int*   orr = (const int*)d_in[6];
    const int*   od  = (const int*)d_in[7];
    float* out = (float*)d_out;

    const int threads = 256;
    const int blocks  = TOTAL_THREADS / threads;  // 4704
    prompter_add_kernel<<<blocks, threads>>>(x, pu, pd, pl, pr, cam, orr, od, out);
}